// round 1
// baseline (speedup 1.0000x reference)
#include <cuda_runtime.h>
#include <math.h>

#define NB   12000
#define Dd   64
#define Bb   1024
#define Ll   20
#define BKk  10
#define NOLDn 20

// ---------------- scratch (device globals; no allocation allowed) ----------
__device__ float g_baskets[4 * Bb * Ll * Dd];   // 20 MB
__device__ float g_s1[4 * Bb * Dd];
__device__ float g_s2[4 * Bb * Dd];
__device__ float g_s3[4 * Bb * Dd];
__device__ float g_lvec[4 * Bb * Dd];
__device__ float g_feach[4 * Bb * Dd];
__device__ float g_Afin[Bb * 128];              // [final | e_user]
__device__ float g_Bmat[128 * NB];              // [e_all^T ; u_w]

__device__ __forceinline__ float sigmoidf(float x) { return 1.f / (1.f + expf(-x)); }

// 64-thread block reduction (broadcast result to all threads)
__device__ __forceinline__ float block64_reduce(float v, float* sbuf, int d) {
    sbuf[d] = v;
    __syncthreads();
    if (d < 32) {
        float r = sbuf[d] + sbuf[d + 32];
#pragma unroll
        for (int o = 16; o > 0; o >>= 1) r += __shfl_down_sync(0xffffffffu, r, o);
        if (d == 0) sbuf[0] = r;
    }
    __syncthreads();
    float r = sbuf[0];
    __syncthreads();
    return r;
}

// ---------------- kernel A: baskets gather-sum ------------------------------
__global__ void k_baskets(const int* __restrict__ click, const int* __restrict__ favor,
                          const int* __restrict__ cart, const int* __restrict__ buy,
                          const float* __restrict__ item_emb) {
    int t = threadIdx.x;
    int d = t & 63;
    int row = blockIdx.x * 4 + (t >> 6);     // row in [0, 4*B*L)
    int n = row / (Bb * Ll);
    int rem = row - n * (Bb * Ll);           // b*L + l
    const int* idx;
    if (n == 0) idx = click; else if (n == 1) idx = favor;
    else if (n == 2) idx = cart; else idx = buy;
    idx += rem * BKk;
    float s = 0.f;
#pragma unroll
    for (int k = 0; k < BKk; k++) s += item_emb[idx[k] * Dd + d];
    g_baskets[row * Dd + d] = s;
}

// ---------------- kernel B: per-(n,b) attention + EMA + gate ----------------
__global__ void __launch_bounds__(64)
k_seq(const int* __restrict__ userData, const float* __restrict__ user_emb,
      const float* __restrict__ user_wd, const float* __restrict__ Wk,
      const float* __restrict__ bk, const float* __restrict__ gate_w,
      const float* __restrict__ gate_b, const float* __restrict__ alpha) {
    int nb = blockIdx.x;                 // n*B + b
    int n = nb / Bb, b = nb - n * Bb;
    int d = threadIdx.x;                 // 0..63

    __shared__ float sb[Ll][Dd];
    __shared__ float sred[Dd];
    __shared__ float s_attn[Ll];

    const float* bas = g_baskets + (size_t)nb * Ll * Dd;
#pragma unroll
    for (int l = 0; l < Ll; l++) sb[l][d] = bas[l * Dd + d];

    float wkreg[Dd];
#pragma unroll
    for (int e = 0; e < Dd; e++) wkreg[e] = Wk[n * Dd * Dd + e * Dd + d];

    int u = userData[b];
    float eu = user_emb[u * Dd + d];
    float bkd = bk[n * Dd + d];
    __syncthreads();

    for (int l = 0; l < Ll; l++) {
        float kd = bkd;
#pragma unroll
        for (int e = 0; e < Dd; e++) kd += sb[l][e] * wkreg[e];
        kd = fmaxf(kd, 0.f);
        float sc = block64_reduce(eu * kd, sred, d);
        float rs = block64_reduce(sb[l][d], sred, d);
        if (d == 0) s_attn[l] = (rs != 0.f) ? sc * 0.125f : -1000000000.0f;
        __syncthreads();
    }

    // softmax over 20 (redundant per thread)
    float m = -3.4e38f;
#pragma unroll
    for (int l = 0; l < Ll; l++) m = fmaxf(m, s_attn[l]);
    float ex[Ll];
    float Z = 0.f;
#pragma unroll
    for (int l = 0; l < Ll; l++) { ex[l] = expf(s_attn[l] - m); Z += ex[l]; }
    float invZ = 1.f / Z;
    float lv = 0.f;
#pragma unroll
    for (int l = 0; l < Ll; l++) lv += ex[l] * invZ * sb[l][d];

    // EMA chains
    float w1 = sigmoidf(user_wd[u * 8 + 2 * n]);
    float w2 = sigmoidf(user_wd[u * 8 + 2 * n + 1]);
    float coef = 1.f - w2 * w1;
    float h1 = sb[0][d];
#pragma unroll
    for (int l = 1; l < Ll; l++) h1 = w1 * h1 + coef * sb[l][d];
    float h2 = sb[Ll / 2][d];
#pragma unroll
    for (int l = Ll / 2 + 1; l < Ll; l++) h2 = w1 * h2 + coef * sb[l][d];
    float h3 = w1 * sb[Ll - 2][d] + coef * sb[Ll - 1][d];

    float a0 = alpha[0], a1 = alpha[1];
    float fn = h1 + a0 * (h1 - h2) + a1 * (h1 - h3);

    float gsum = block64_reduce(fn * gate_w[d] + lv * gate_w[Dd + d], sred, d);
    float g = sigmoidf(gsum + gate_b[0]);
    float fe = g * fn + (1.f - g) * lv;

    int off = nb * Dd + d;
    g_s1[off] = h1; g_s2[off] = h2; g_s3[off] = h3;
    g_lvec[off] = lv; g_feach[off] = fe;
}

// ---------------- kernel C: mixture over behaviors --------------------------
__global__ void __launch_bounds__(64)
k_mix(const int* __restrict__ userData, const float* __restrict__ user_emb,
      const float* __restrict__ w_mix, const float* __restrict__ alpha,
      const float* __restrict__ gate_w, const float* __restrict__ gate_b) {
    int b = blockIdx.x;
    int d = threadIdx.x;
    __shared__ float sred[Dd];

    // softmax rows of w_mix (tiny, redundant per thread)
    float w[4][4];
#pragma unroll
    for (int i = 0; i < 4; i++) {
        float mx = -3.4e38f;
#pragma unroll
        for (int j = 0; j < 4; j++) mx = fmaxf(mx, w_mix[i * 4 + j]);
        float Z = 0.f;
#pragma unroll
        for (int j = 0; j < 4; j++) { w[i][j] = expf(w_mix[i * 4 + j] - mx); Z += w[i][j]; }
        float inv = 1.f / Z;
#pragma unroll
        for (int j = 0; j < 4; j++) w[i][j] *= inv;
    }

    float s1m = 0.f, s2m = 0.f, s3m = 0.f, lm = 0.f;
#pragma unroll
    for (int n = 0; n < 4; n++) {
        int off = (n * Bb + b) * Dd + d;
        s1m += w[0][n] * g_s1[off];
        s2m += w[1][n] * g_s2[off];
        s3m += w[2][n] * g_s3[off];
        lm  += w[3][n] * g_lvec[off];
    }
    float a0 = alpha[0], a1 = alpha[1];
    float fin_ = s1m + a0 * (s1m - s2m) + a1 * (s1m - s3m);

    float gsum = block64_reduce(fin_ * gate_w[d] + lm * gate_w[Dd + d], sred, d);
    float gm = sigmoidf(gsum + gate_b[0]);
    float fin = gm * fin_ + (1.f - gm) * lm;

    g_Afin[b * 128 + d] = fin;
    g_Afin[b * 128 + Dd + d] = user_emb[userData[b] * Dd + d];
}

// ---------------- kernel: build fused B matrix [e_all^T ; u_w] --------------
__global__ void k_bmat(const float* __restrict__ item_emb, const float* __restrict__ u_w) {
    int i = blockIdx.x * blockDim.x + threadIdx.x;
    if (i >= 128 * NB) return;
    int k = i / NB, e = i - k * NB;
    g_Bmat[i] = (k < Dd) ? item_emb[(e + 1) * Dd + k] : u_w[(k - Dd) * NB + e];
}

// ---------------- kernel D: score GEMM (M=1024, N=12000, K=128) -------------
__global__ void __launch_bounds__(256)
k_score(const float* __restrict__ u_b, float* __restrict__ out) {
    __shared__ float As[32][132];   // As[k][row]
    __shared__ float Bs[32][132];   // Bs[k][col]
    int t = threadIdx.x;
    int i0 = blockIdx.y * 128, j0 = blockIdx.x * 128;
    int tx = t & 15, ty = t >> 4;
    float acc[8][8];
#pragma unroll
    for (int m = 0; m < 8; m++)
#pragma unroll
        for (int nn = 0; nn < 8; nn++) acc[m][nn] = 0.f;

    for (int kc = 0; kc < 128; kc += 32) {
#pragma unroll
        for (int it = 0; it < 16; it++) {
            int idx = it * 256 + t;
            int r = idx >> 5, kk = idx & 31;
            As[kk][r] = g_Afin[(i0 + r) * 128 + kc + kk];
        }
#pragma unroll
        for (int it = 0; it < 16; it++) {
            int idx = it * 256 + t;
            int kk = idx >> 7, e = idx & 127;
            int j = j0 + e;
            Bs[kk][e] = (j < NB) ? g_Bmat[(kc + kk) * NB + j] : 0.f;
        }
        __syncthreads();
#pragma unroll
        for (int kk = 0; kk < 32; kk++) {
            float a[8], bb[8];
            *(float4*)&a[0] = *(const float4*)&As[kk][ty * 8];
            *(float4*)&a[4] = *(const float4*)&As[kk][ty * 8 + 4];
            *(float4*)&bb[0] = *(const float4*)&Bs[kk][tx * 8];
            *(float4*)&bb[4] = *(const float4*)&Bs[kk][tx * 8 + 4];
#pragma unroll
            for (int m = 0; m < 8; m++)
#pragma unroll
                for (int nn = 0; nn < 8; nn++) acc[m][nn] += a[m] * bb[nn];
        }
        __syncthreads();
    }
#pragma unroll
    for (int m = 0; m < 8; m++) {
        int i = i0 + ty * 8 + m;
#pragma unroll
        for (int n4 = 0; n4 < 8; n4 += 4) {
            int j = j0 + tx * 8 + n4;
            if (j < NB) {
                float4 v;
                v.x = acc[m][n4 + 0] + u_b[j + 0];
                v.y = acc[m][n4 + 1] + u_b[j + 1];
                v.z = acc[m][n4 + 2] + u_b[j + 2];
                v.w = acc[m][n4 + 3] + u_b[j + 3];
                *(float4*)&out[(size_t)i * NB + j] = v;
            }
        }
    }
}

// ---------------- kernel E: sim = e_all @ e_all^T (triangular grid) ---------
__global__ void __launch_bounds__(256)
k_sim(const float* __restrict__ item_emb, float* __restrict__ out) {
    __shared__ float As[32][132];
    __shared__ float Bs[32][132];
    int lid = blockIdx.x;
    // decode linear id -> (bi <= bj) upper-triangle tile pair
    int r = (int)((sqrtf(8.f * (float)lid + 1.f) - 1.f) * 0.5f);
    while ((r + 1) * (r + 2) / 2 <= lid) r++;
    while (r * (r + 1) / 2 > lid) r--;
    int bi = lid - r * (r + 1) / 2;   // <= r
    int bj = r;
    int i0 = bi * 128, j0 = bj * 128;

    const float* eall = item_emb + Dd;   // row e -> item_emb[(e+1)*64]
    int t = threadIdx.x;
    int tx = t & 15, ty = t >> 4;
    float acc[8][8];
#pragma unroll
    for (int m = 0; m < 8; m++)
#pragma unroll
        for (int nn = 0; nn < 8; nn++) acc[m][nn] = 0.f;

    for (int kc = 0; kc < 64; kc += 32) {
#pragma unroll
        for (int it = 0; it < 16; it++) {
            int idx = it * 256 + t;
            int rr = idx >> 5, kk = idx & 31;
            int gi = i0 + rr; if (gi > NB - 1) gi = NB - 1;
            As[kk][rr] = eall[gi * Dd + kc + kk];
        }
#pragma unroll
        for (int it = 0; it < 16; it++) {
            int idx = it * 256 + t;
            int rr = idx >> 5, kk = idx & 31;
            int gj = j0 + rr; if (gj > NB - 1) gj = NB - 1;
            Bs[kk][rr] = eall[gj * Dd + kc + kk];
        }
        __syncthreads();
#pragma unroll
        for (int kk = 0; kk < 32; kk++) {
            float a[8], bb[8];
            *(float4*)&a[0] = *(const float4*)&As[kk][ty * 8];
            *(float4*)&a[4] = *(const float4*)&As[kk][ty * 8 + 4];
            *(float4*)&bb[0] = *(const float4*)&Bs[kk][tx * 8];
            *(float4*)&bb[4] = *(const float4*)&Bs[kk][tx * 8 + 4];
#pragma unroll
            for (int m = 0; m < 8; m++)
#pragma unroll
                for (int nn = 0; nn < 8; nn++) acc[m][nn] += a[m] * bb[nn];
        }
        __syncthreads();
    }

    // direct store (bi,bj)
#pragma unroll
    for (int m = 0; m < 8; m++) {
        int i = i0 + ty * 8 + m;
        if (i < NB) {
#pragma unroll
            for (int n4 = 0; n4 < 8; n4 += 4) {
                int j = j0 + tx * 8 + n4;
                if (j < NB) {
                    float4 v = make_float4(acc[m][n4], acc[m][n4 + 1], acc[m][n4 + 2], acc[m][n4 + 3]);
                    *(float4*)&out[(size_t)i * NB + j] = v;
                }
            }
        }
    }
    // mirrored store (bj,bi) for off-diagonal tiles
    if (bi != bj) {
#pragma unroll
        for (int nn = 0; nn < 8; nn++) {
            int j = j0 + tx * 8 + nn;
            if (j < NB) {
                float4 v0 = make_float4(acc[0][nn], acc[1][nn], acc[2][nn], acc[3][nn]);
                float4 v1 = make_float4(acc[4][nn], acc[5][nn], acc[6][nn], acc[7][nn]);
                *(float4*)&out[(size_t)j * NB + i0 + ty * 8] = v0;
                *(float4*)&out[(size_t)j * NB + i0 + ty * 8 + 4] = v1;
            }
        }
    }
}

// ---------------- kernel G: sparse old-items corrections --------------------
__global__ void __launch_bounds__(128)
k_sparse(const int* __restrict__ oldItems, const float* __restrict__ item_emb,
         float* __restrict__ out) {
    int b = blockIdx.x;
    int t = threadIdx.x;
    int n = t >> 5, lane = t & 31;
    __shared__ int sh_old[4][NOLDn];
    __shared__ float sh_fin[Dd];
    if (t < Dd) sh_fin[t] = g_Afin[b * 128 + t];
    if (t < 4 * NOLDn) {
        int n2 = t / NOLDn, j = t - n2 * NOLDn;
        sh_old[n2][j] = oldItems[(n2 * Bb + b) * NOLDn + j];
    }
    __syncthreads();

    int d0 = lane, d1 = lane + 32;
    float diff0 = g_feach[(n * Bb + b) * Dd + d0] - sh_fin[d0];
    float diff1 = g_feach[(n * Bb + b) * Dd + d1] - sh_fin[d1];
    const float* eall = item_emb + Dd;

    for (int j = 0; j < NOLDn; j++) {
        int e = sh_old[n][j];
        bool dup = false;
        for (int j2 = 0; j2 < j; j2++) if (sh_old[n][j2] == e) dup = true;
        if (dup) continue;
        float v = diff0 * eall[e * Dd + d0] + diff1 * eall[e * Dd + d1];
#pragma unroll
        for (int o = 16; o > 0; o >>= 1) v += __shfl_down_sync(0xffffffffu, v, o);
        if (lane == 0) atomicAdd(&out[(size_t)b * NB + e], v);
    }
}

// ---------------- kernel F: omiga copy ---------------------------------------
__global__ void k_omiga(const float* __restrict__ omiga, float* __restrict__ out) {
    int i = blockIdx.x * blockDim.x + threadIdx.x;
    if (i < NB) out[i] = omiga[i + 1];
}

// ---------------- launch ------------------------------------------------------
extern "C" void kernel_launch(void* const* d_in, const int* in_sizes, int n_in,
                              void* d_out, int out_size) {
    const int* click = (const int*)d_in[0];
    const int* favor = (const int*)d_in[1];
    const int* cart  = (const int*)d_in[2];
    const int* buy   = (const int*)d_in[3];
    const int* user  = (const int*)d_in[4];
    const int* olds  = (const int*)d_in[5];
    const float* item_emb = (const float*)d_in[6];
    const float* user_emb = (const float*)d_in[7];
    const float* user_wd  = (const float*)d_in[8];
    const float* omiga    = (const float*)d_in[9];
    const float* w_mix    = (const float*)d_in[10];
    const float* alpha    = (const float*)d_in[11];
    const float* gate_w   = (const float*)d_in[12];
    const float* gate_b   = (const float*)d_in[13];
    const float* Wk       = (const float*)d_in[14];
    const float* bk       = (const float*)d_in[15];
    const float* u_w      = (const float*)d_in[16];
    const float* u_b      = (const float*)d_in[17];
    float* out = (float*)d_out;

    k_baskets<<<4 * Bb * Ll / 4, 256>>>(click, favor, cart, buy, item_emb);
    k_seq<<<4 * Bb, 64>>>(user, user_emb, user_wd, Wk, bk, gate_w, gate_b, alpha);
    k_mix<<<Bb, 64>>>(user, user_emb, w_mix, alpha, gate_w, gate_b);
    k_bmat<<<(128 * NB + 255) / 256, 256>>>(item_emb, u_w);

    dim3 gs((NB + 127) / 128, Bb / 128);
    k_score<<<gs, 256>>>(u_b, out);
    k_sparse<<<Bb, 128>>>(olds, item_emb, out);

    int nbT = (NB + 127) / 128;               // 94
    k_sim<<<nbT * (nbT + 1) / 2, 256>>>(item_emb, out + (size_t)Bb * NB);
    k_omiga<<<(NB + 255) / 256, 256>>>(omiga, out + (size_t)Bb * NB + (size_t)NB * NB);
}